// round 16
// baseline (speedup 1.0000x reference)
#include <cuda_runtime.h>
#include <cuda_fp16.h>
#include <cstddef>
#include <cstdint>

// ============================================================================
// SmalldeckClassificationFlat — fp16 HMMA, 128-thread CTAs.
//   R15: layer1+layer2 FUSED (intermediate 16x512 kept in smem, never hits
//   DRAM). o1 split-K=2 BM=32; o2 BM=16; o3 BM=16 + fused 127->9 scorer.
// ============================================================================

#define EMBD 64
static constexpr int MAXM = 2048;

// --------------------- activation scratch (fp16) ----------------------------
static constexpr size_t A_HEROIN  = 0;
static constexpr size_t S_HEROIN  = (size_t)MAXM * 6 * 128;
static constexpr size_t A_BOARDIN = A_HEROIN + S_HEROIN;
static constexpr size_t S_BOARDIN = (size_t)MAXM * 10 * 192;
static constexpr size_t A_X       = A_BOARDIN + S_BOARDIN;
static constexpr size_t S_X       = (size_t)MAXM * 2048;
static constexpr size_t A_O1      = A_X + S_X;
static constexpr size_t S_O1      = (size_t)MAXM * 512;
static constexpr size_t A_O2      = A_O1 + S_O1;
static constexpr size_t S_O2      = (size_t)MAXM * 256;
static constexpr size_t A_TOT     = A_O2 + S_O2;
__device__ __align__(256) __half g_ah[A_TOT];

// --------------------------- weight scratch (fp16) --------------------------
static constexpr size_t W_HW1 = 0;                       // 512x128
static constexpr size_t W_HW2 = W_HW1 + 512 * 128;       // 128x512
static constexpr size_t W_BW1 = W_HW2 + 128 * 512;       // 512x192
static constexpr size_t W_BW2 = W_BW1 + 512 * 192;       // 128x512
static constexpr size_t W_WF  = W_BW2 + 128 * 512;       // 512x2048 (fold, fused)
static constexpr size_t W_OW2 = W_WF  + 512 * 2048;      // 256x512
static constexpr size_t W_OW3 = W_OW2 + 256 * 512;       // 128x256 (row 127 zero)
static constexpr size_t W_TOT = W_OW3 + 128 * 256;
__device__ __align__(256) __half g_wh[W_TOT];

// split-K partials for o1: 2 x [2048 x 512] fp32
__device__ __align__(256) float g_part[2 * MAXM * 512];

__constant__ int HP[6][2]  = {{0,1},{0,2},{0,3},{1,2},{1,3},{2,3}};
__constant__ int BT[10][3] = {{0,1,2},{0,1,3},{0,1,4},{0,2,3},{0,2,4},
                              {0,3,4},{1,2,3},{1,2,4},{1,3,4},{2,3,4}};

// ------------------------------ PTX helpers ---------------------------------
__device__ __forceinline__ uint32_t smem_to_u32(const void* p) {
    uint32_t a;
    asm("{ .reg .u64 t; cvta.to.shared.u64 t, %1; cvt.u32.u64 %0, t; }" : "=r"(a) : "l"(p));
    return a;
}
__device__ __forceinline__ void cp_async16(uint32_t dst, const void* src) {
    asm volatile("cp.async.cg.shared.global [%0], [%1], 16;\n" :: "r"(dst), "l"(src));
}
__device__ __forceinline__ void cp_commit() {
    asm volatile("cp.async.commit_group;\n" ::: "memory");
}
template <int N>
__device__ __forceinline__ void cp_wait() {
    asm volatile("cp.async.wait_group %0;\n" :: "n"(N) : "memory");
}
__device__ __forceinline__ void ldm4(uint32_t (&r)[4], uint32_t a) {
    asm volatile("ldmatrix.sync.aligned.m8n8.x4.shared.b16 {%0,%1,%2,%3}, [%4];"
                 : "=r"(r[0]), "=r"(r[1]), "=r"(r[2]), "=r"(r[3]) : "r"(a));
}
__device__ __forceinline__ void mma16816(float (&d)[4], const uint32_t (&a)[4],
                                         uint32_t b0, uint32_t b1) {
    asm volatile(
        "mma.sync.aligned.m16n8k16.row.col.f32.f16.f16.f32 "
        "{%0,%1,%2,%3}, {%4,%5,%6,%7}, {%8,%9}, {%0,%1,%2,%3};"
        : "+f"(d[0]), "+f"(d[1]), "+f"(d[2]), "+f"(d[3])
        : "r"(a[0]), "r"(a[1]), "r"(a[2]), "r"(a[3]), "r"(b0), "r"(b1));
}

// ----------------------------------------------------------------------------
// prep: 4 rows per block (256 threads), sort cards, gather embeddings -> fp16
// ----------------------------------------------------------------------------
__global__ void prep_kernel(const int* __restrict__ x, const float* __restrict__ emb,
                            __half* __restrict__ ah)
{
    int t  = threadIdx.x;
    int lr = t >> 6;
    int c  = t & 63;
    int m  = blockIdx.x * 4 + lr;

    __shared__ int   cid[4][9];
    __shared__ float e9[4][9][EMBD];

    if (c == 0) {
        int key[9], cc[9];
        #pragma unroll
        for (int i = 0; i < 9; i++) {
            int rk = x[m * 18 + 2 * i];
            int st = x[m * 18 + 2 * i + 1];
            key[i] = rk * 8 + st;
            cc[i]  = (rk - 1) * st;
        }
        for (int i = 1; i < 4; i++) {
            int k = key[i], v = cc[i], j = i - 1;
            while (j >= 0 && key[j] > k) { key[j+1] = key[j]; cc[j+1] = cc[j]; j--; }
            key[j+1] = k; cc[j+1] = v;
        }
        for (int i = 5; i < 9; i++) {
            int k = key[i], v = cc[i], j = i - 1;
            while (j >= 4 && key[j] > k) { key[j+1] = key[j]; cc[j+1] = cc[j]; j--; }
            key[j+1] = k; cc[j+1] = v;
        }
        #pragma unroll
        for (int i = 0; i < 9; i++) cid[lr][i] = cc[i];
    }
    __syncthreads();

    #pragma unroll
    for (int i = 0; i < 9; i++) e9[lr][i][c] = emb[cid[lr][i] * EMBD + c];

    #pragma unroll
    for (int hh = 0; hh < 6; hh++) {
        size_t base = A_HEROIN + ((size_t)m * 6 + hh) * 128;
        ah[base + c]      = __float2half_rn(e9[lr][HP[hh][0]][c]);
        ah[base + 64 + c] = __float2half_rn(e9[lr][HP[hh][1]][c]);
    }
    #pragma unroll
    for (int b = 0; b < 10; b++) {
        size_t base = A_BOARDIN + ((size_t)m * 10 + b) * 192;
        ah[base + c]       = __float2half_rn(e9[lr][4 + BT[b][0]][c]);
        ah[base + 64 + c]  = __float2half_rn(e9[lr][4 + BT[b][1]][c]);
        ah[base + 128 + c] = __float2half_rn(e9[lr][4 + BT[b][2]][c]);
    }
}

// ----------------------------------------------------------------------------
// prep_w: z<6 -> transpose+fp16 weight; z==6 -> fused fold of oW1 into W_WF
// ----------------------------------------------------------------------------
struct TD { const float* src; __half* dh; int K, N, Npad; };
struct TDArr { TD d[6]; };

__global__ void prep_w_kernel(TDArr descs, const float* __restrict__ oW1,
                              __half* __restrict__ whBase)
{
    int tx = threadIdx.x, ty = threadIdx.y;
    if (blockIdx.z == 6) {
        int r0 = blockIdx.x * 32, n0 = blockIdx.y * 32;
        __shared__ float t[32][33];
        #pragma unroll
        for (int j = 0; j < 4; j++) {
            int r = r0 + ty + 8 * j;
            int n = n0 + tx;
            float s = 0.f;
            if (r < 768) {
                int h = r >> 7, k = r & 127;
                #pragma unroll
                for (int b = 0; b < 10; b++)
                    s += oW1[((size_t)((h * 10 + b) * 256 + k)) * 512 + n];
            } else {
                int rb = r - 768;
                int b = rb >> 7, k = rb & 127;
                #pragma unroll
                for (int h = 0; h < 6; h++)
                    s += oW1[((size_t)((h * 10 + b) * 256 + 128 + k)) * 512 + n];
            }
            t[ty + 8 * j][tx] = s;
        }
        __syncthreads();
        #pragma unroll
        for (int j = 0; j < 4; j++) {
            int nl = ty + 8 * j;
            whBase[W_WF + (size_t)(n0 + nl) * 2048 + r0 + tx] = __float2half_rn(t[tx][nl]);
        }
    } else {
        TD d = descs.d[blockIdx.z];
        int kt = blockIdx.x * 32, nt = blockIdx.y * 32;
        if (kt >= d.K || nt >= d.Npad) return;
        __shared__ float tile[32][33];
        for (int i = ty; i < 32; i += 8) {
            int k = kt + i, n = nt + tx;
            float v = (k < d.K && n < d.N) ? d.src[(size_t)k * d.N + n] : 0.f;
            tile[i][tx] = v;
        }
        __syncthreads();
        for (int i = ty; i < 32; i += 8) {
            int n = nt + i, k = kt + tx;
            if (n < d.Npad && k < d.K)
                d.dh[(size_t)n * d.K + k] = __float2half_rn(tile[tx][i]);
        }
    }
}

// ----------------------------------------------------------------------------
// FUSED layer1+layer2 kernel. BM=16 rows of the hero/board stream.
// Phase 1: X1[16][512] = lrelu(A@W1^T + b1), looped over 4 N-chunks of 128,
//          written to smem XI in chunked 80B-row layout (16 chunks of K=32).
// Phase 2: out[16][128] = lrelu(X1@W2^T + b2), A from XI, scatter into X.
// 128 threads (4 warps, all N-warps). smem: 3 stages + XI.
// ----------------------------------------------------------------------------
struct FuseP {
    const __half* Ain;   // [rows][K1]
    const __half* W1;    // [512][K1]
    const float* b1;     // [512]
    const __half* W2;    // [128][512]
    const float* b2;     // [128]
    __half* Xout;
    int K1;              // 128 (hero) or 192 (board)
    int divv, ldOut, seg, yb;
};

static constexpr int F_ROWB = 80;
static constexpr int F_SA   = 16 * F_ROWB;          // 1280
static constexpr int F_SB   = 128 * F_ROWB;         // 10240
static constexpr int F_STG  = F_SA + F_SB;          // 11520
static constexpr int F_XI   = 3 * F_STG;            // 34560
static constexpr int F_SMEM = F_XI + 16 * F_SA;     // 34560 + 20480 = 55040

__global__ void __launch_bounds__(128, 4) fused12_kernel(FuseP p0, FuseP p1)
{
    bool first = (blockIdx.y < (unsigned)p0.yb);
    FuseP p = first ? p0 : p1;
    int my = first ? blockIdx.y : (blockIdx.y - p0.yb);

    extern __shared__ char smem[];
    uint32_t sbase  = smem_to_u32(smem);
    uint32_t xibase = sbase + F_XI;

    int tid = threadIdx.x, lane = tid & 31, wx = tid >> 5;   // 4 N-warps
    int m0 = my * 16;
    int K1 = p.K1;
    int KC = K1 >> 5;                 // 4 or 6 k-chunks per N-chunk

    auto load1 = [&](int nc, int k0, int st) {
        uint32_t s0 = sbase + (uint32_t)st * F_STG;
        if (tid < 64) {
            int row = tid >> 2, c = tid & 3;
            cp_async16(s0 + row * F_ROWB + c * 16,
                       p.Ain + (size_t)(m0 + row) * K1 + k0 + c * 8);
        }
        #pragma unroll
        for (int i = tid; i < 512; i += 128) {
            int row = i >> 2, c = i & 3;
            cp_async16(s0 + F_SA + row * F_ROWB + c * 16,
                       p.W1 + (size_t)(nc * 128 + row) * K1 + k0 + c * 8);
        }
    };
    auto load2 = [&](int ch, int st) {
        uint32_t s0 = sbase + (uint32_t)st * F_STG;
        int k0 = ch * 32;
        #pragma unroll
        for (int i = tid; i < 512; i += 128) {
            int row = i >> 2, c = i & 3;
            cp_async16(s0 + F_SA + row * F_ROWB + c * 16,
                       p.W2 + (size_t)row * 512 + k0 + c * 8);
        }
    };

    uint32_t a_off = (uint32_t)((lane & 15) * F_ROWB + (lane >> 4) * 16);
    uint32_t b_off = (uint32_t)(F_SA + (wx * 32 + (lane & 7)) * F_ROWB
                                + ((lane >> 3) & 3) * 16);

    float acc[4][4];
    #pragma unroll
    for (int j = 0; j < 4; j++)
        #pragma unroll
        for (int q = 0; q < 4; q++) acc[j][q] = 0.f;

    // ---- phase 1 ----
    int total1 = 4 * KC;
    {
        int nc = 0, k0 = 0;
        load1(nc, k0, 0); cp_commit();
        nc = 1 / KC; k0 = (1 - nc * KC) * 32;
        load1(nc, k0, 1); cp_commit();
    }
    for (int ch = 0; ch < total1; ch++) {
        cp_wait<1>();
        __syncthreads();
        if (ch + 2 < total1) {
            int nc = (ch + 2) / KC, k0 = ((ch + 2) - nc * KC) * 32;
            load1(nc, k0, (ch + 2) % 3);
        }
        cp_commit();

        uint32_t s0 = sbase + (uint32_t)(ch % 3) * F_STG;
        uint32_t bf[4][4];
        #pragma unroll
        for (int ni = 0; ni < 4; ni++)
            ldm4(bf[ni], s0 + b_off + ni * (8 * F_ROWB));
        #pragma unroll
        for (int k16 = 0; k16 < 2; k16++) {
            uint32_t af[4];
            ldm4(af, s0 + a_off + k16 * 32);
            #pragma unroll
            for (int ni = 0; ni < 4; ni++)
                mma16816(acc[ni], af, bf[ni][2 * k16], bf[ni][2 * k16 + 1]);
        }

        if ((ch + 1) % KC == 0) {   // finished this N-chunk
            int nc = ch / KC;
            #pragma unroll
            for (int ni = 0; ni < 4; ni++) {
                int nl = wx * 32 + ni * 8 + 2 * (lane & 3);
                int n  = nc * 128 + nl;
                float bv0 = p.b1[n], bv1 = p.b1[n + 1];
                #pragma unroll
                for (int half = 0; half < 2; half++) {
                    int r = (lane >> 2) + half * 8;
                    float v0 = acc[ni][half * 2 + 0] + bv0;
                    float v1 = acc[ni][half * 2 + 1] + bv1;
                    v0 = (v0 > 0.f) ? v0 : 0.01f * v0;
                    v1 = (v1 > 0.f) ? v1 : 0.01f * v1;
                    int c = n >> 5, col = n & 31;
                    *reinterpret_cast<__half2*>(smem + F_XI + c * F_SA + r * F_ROWB + col * 2)
                        = __floats2half2_rn(v0, v1);
                }
            }
            #pragma unroll
            for (int j = 0; j < 4; j++)
                #pragma unroll
                for (int q = 0; q < 4; q++) acc[j][q] = 0.f;
        }
    }

    cp_wait<0>();
    __syncthreads();   // XI fully written, visible to all warps

    // ---- phase 2: K=512, 16 chunks, A from XI ----
    load2(0, 0); cp_commit();
    load2(1, 1); cp_commit();
    for (int ch = 0; ch < 16; ch++) {
        cp_wait<1>();
        __syncthreads();
        if (ch + 2 < 16) load2(ch + 2, (ch + 2) % 3);
        cp_commit();

        uint32_t s0 = sbase + (uint32_t)(ch % 3) * F_STG;
        uint32_t bf[4][4];
        #pragma unroll
        for (int ni = 0; ni < 4; ni++)
            ldm4(bf[ni], s0 + b_off + ni * (8 * F_ROWB));
        uint32_t xich = xibase + ch * F_SA;
        #pragma unroll
        for (int k16 = 0; k16 < 2; k16++) {
            uint32_t af[4];
            ldm4(af, xich + a_off + k16 * 32);
            #pragma unroll
            for (int ni = 0; ni < 4; ni++)
                mma16816(acc[ni], af, bf[ni][2 * k16], bf[ni][2 * k16 + 1]);
        }
    }

    // ---- epilogue: scatter into X ----
    #pragma unroll
    for (int ni = 0; ni < 4; ni++) {
        int n = wx * 32 + ni * 8 + 2 * (lane & 3);
        float bv0 = p.b2[n], bv1 = p.b2[n + 1];
        #pragma unroll
        for (int half = 0; half < 2; half++) {
            int r = m0 + (lane >> 2) + half * 8;
            float v0 = acc[ni][half * 2 + 0] + bv0;
            float v1 = acc[ni][half * 2 + 1] + bv1;
            v0 = (v0 > 0.f) ? v0 : 0.01f * v0;
            v1 = (v1 > 0.f) ? v1 : 0.01f * v1;
            size_t base = (size_t)(r / p.divv) * p.ldOut + p.seg
                        + (size_t)(r % p.divv) * 128 + n;
            *reinterpret_cast<__half2*>(p.Xout + base) = __floats2half2_rn(v0, v1);
        }
    }
}

// ----------------------------------------------------------------------------
// HMMA GEMM (unchanged machinery), BM=32 (o1) / BM=16 (o2, o3+scorer).
// ----------------------------------------------------------------------------
struct GemmP {
    const __half* Ah; const __half* Bh;
    const float* bias; int nbias;
    __half* Ch; float* Cp;
    int Kst;
    int kcnt;
    int divv, ldOut, seg, yb;
    size_t pstride;
    const float* sW; const float* sb; float* outp;
};

template<int BM, bool FINAL>
__global__ void __launch_bounds__(128, 4) hmma_gemm(GemmP p0, GemmP p1)
{
    constexpr int ROWB = 80;
    constexpr int SA = BM * ROWB;
    constexpr int SB = 128 * ROWB;
    constexpr int STG = SA + SB;
    constexpr int MW = (BM >= 64) ? 2 : 1;
    constexpr int NWARP = 4 / MW;
    constexpr int WN = 128 / NWARP;
    constexpr int NF = WN / 8;
    constexpr int WROWS = BM / MW;
    constexpr int MF = WROWS / 16;

    bool first = (blockIdx.y < (unsigned)p0.yb);
    GemmP p = first ? p0 : p1;
    int my = first ? blockIdx.y : (blockIdx.y - p0.yb);

    extern __shared__ char smem[];
    uint32_t sbase = smem_to_u32(smem);

    int tid = threadIdx.x, lane = tid & 31, wid = tid >> 5;
    int wy = wid / NWARP, wx = wid % NWARP;
    int m0 = my * BM, n0 = blockIdx.x * 128;
    int Kst = p.Kst;
    int kbeg = blockIdx.z * p.kcnt;

    float* sWs = reinterpret_cast<float*>(smem + 3 * STG);
    float* sbs = sWs + 1143;
    if (FINAL) {
        for (int i = tid; i < 1143; i += 128) sWs[i] = p.sW[i];
        if (tid < 9) sbs[tid] = p.sb[tid];
    }

    float acc[MF][NF][4];
    #pragma unroll
    for (int i = 0; i < MF; i++)
        #pragma unroll
        for (int j = 0; j < NF; j++)
            #pragma unroll
            for (int q = 0; q < 4; q++) acc[i][j][q] = 0.f;

    auto load_stage = [&](int k0, int st) {
        uint32_t s0 = sbase + (uint32_t)st * STG;
        #pragma unroll
        for (int i = tid; i < BM * 4; i += 128) {
            int row = i >> 2, c = i & 3;
            size_t go = (size_t)(m0 + row) * Kst + kbeg + k0 + c * 8;
            cp_async16(s0 + row * ROWB + c * 16, p.Ah + go);
        }
        #pragma unroll
        for (int i = tid; i < 512; i += 128) {
            int row = i >> 2, c = i & 3;
            size_t go = (size_t)(n0 + row) * Kst + kbeg + k0 + c * 8;
            cp_async16(s0 + SA + row * ROWB + c * 16, p.Bh + go);
        }
    };

    uint32_t a_off = (uint32_t)((wy * WROWS + (lane & 15)) * ROWB + (lane >> 4) * 16);
    uint32_t b_off = (uint32_t)(SA + (wx * WN + (lane & 7)) * ROWB + ((lane >> 3) & 3) * 16);

    int nch = p.kcnt >> 5;
    load_stage(0, 0);
    cp_commit();
    if (nch > 1) load_stage(32, 1);
    cp_commit();

    for (int ch = 0; ch < nch; ch++) {
        cp_wait<1>();
        __syncthreads();
        if (ch + 2 < nch) load_stage((ch + 2) << 5, (ch + 2) % 3);
        cp_commit();

        uint32_t s0 = sbase + (uint32_t)(ch % 3) * STG;

        uint32_t bf[NF][4];
        #pragma unroll
        for (int ni = 0; ni < NF; ni++)
            ldm4(bf[ni], s0 + b_off + ni * (8 * ROWB));

        #pragma unroll
        for (int k16 = 0; k16 < 2; k16++) {
            #pragma unroll
            for (int mi = 0; mi < MF; mi++) {
                uint32_t af[4];
                ldm4(af, s0 + a_off + mi * (16 * ROWB) + k16 * 32);
                #pragma unroll
                for (int ni = 0; ni < NF; ni++)
                    mma16816(acc[mi][ni], af, bf[ni][2 * k16], bf[ni][2 * k16 + 1]);
            }
        }
    }

    if (FINAL) {
        float* sm = reinterpret_cast<float*>(smem);      // [BM][132]
        __syncthreads();
        #pragma unroll
        for (int mi = 0; mi < MF; mi++) {
            #pragma unroll
            for (int ni = 0; ni < NF; ni++) {
                int n = wx * WN + ni * 8 + 2 * (lane & 3);
                float bv0 = (n < p.nbias) ? p.bias[n] : 0.f;
                float bv1 = (n + 1 < p.nbias) ? p.bias[n + 1] : 0.f;
                #pragma unroll
                for (int half = 0; half < 2; half++) {
                    int r = wy * WROWS + mi * 16 + (lane >> 2) + half * 8;
                    float v0 = acc[mi][ni][half * 2 + 0] + bv0;
                    float v1 = acc[mi][ni][half * 2 + 1] + bv1;
                    v0 = (v0 > 0.f) ? v0 : 0.01f * v0;
                    v1 = (v1 > 0.f) ? v1 : 0.01f * v1;
                    sm[r * 132 + n] = v0;
                    sm[r * 132 + n + 1] = v1;
                }
            }
        }
        __syncthreads();
        for (int idx = tid; idx < BM * 9; idx += 128) {
            int r = idx / 9, n = idx - r * 9;
            float a = sbs[n];
            #pragma unroll 1
            for (int k = 0; k < 127; k++) a += sm[r * 132 + k] * sWs[k * 9 + n];
            p.outp[(size_t)(m0 + r) * 9 + n] = a;
        }
        return;
    }

    #pragma unroll
    for (int mi = 0; mi < MF; mi++) {
        #pragma unroll
        for (int ni = 0; ni < NF; ni++) {
            int n = n0 + wx * WN + ni * 8 + 2 * (lane & 3);
            #pragma unroll
            for (int half = 0; half < 2; half++) {
                int r = m0 + wy * WROWS + mi * 16 + (lane >> 2) + half * 8;
                float v0 = acc[mi][ni][half * 2 + 0];
                float v1 = acc[mi][ni][half * 2 + 1];
                if (p.Cp) {
                    *reinterpret_cast<float2*>(p.Cp + blockIdx.z * p.pstride
                        + (size_t)r * p.ldOut + n) = make_float2(v0, v1);
                } else {
                    float bv0 = (n < p.nbias) ? p.bias[n] : 0.f;
                    float bv1 = (n + 1 < p.nbias) ? p.bias[n + 1] : 0.f;
                    v0 += bv0; v1 += bv1;
                    v0 = (v0 > 0.f) ? v0 : 0.01f * v0;
                    v1 = (v1 > 0.f) ? v1 : 0.01f * v1;
                    size_t base;
                    if (p.divv == 0) base = (size_t)r * p.ldOut + n;
                    else base = (size_t)(r / p.divv) * p.ldOut + p.seg
                              + (size_t)(r % p.divv) * 128 + n;
                    *reinterpret_cast<__half2*>(p.Ch + base) = __floats2half2_rn(v0, v1);
                }
            }
        }
    }
}

// ----------------------------------------------------------------------------
// reduce for o1 split-K=2: O1 = lrelu(p0+p1 + bias) -> fp16, 4 elems/thread
// ----------------------------------------------------------------------------
__global__ void reduce_o1_kernel(const float* __restrict__ Cp, const float* __restrict__ bias,
                                 __half* __restrict__ O1, size_t pstride, int total4)
{
    int i4 = blockIdx.x * 256 + threadIdx.x;
    if (i4 >= total4) return;
    int i = i4 * 4;
    float4 a = *reinterpret_cast<const float4*>(Cp + i);
    float4 b = *reinterpret_cast<const float4*>(Cp + pstride + i);
    int nb = i & 511;
    float v0 = a.x + b.x + bias[nb + 0];
    float v1 = a.y + b.y + bias[nb + 1];
    float v2 = a.z + b.z + bias[nb + 2];
    float v3 = a.w + b.w + bias[nb + 3];
    v0 = (v0 > 0.f) ? v0 : 0.01f * v0;
    v1 = (v1 > 0.f) ? v1 : 0.01f * v1;
    v2 = (v2 > 0.f) ? v2 : 0.01f * v2;
    v3 = (v3 > 0.f) ? v3 : 0.01f * v3;
    __half2 h0 = __floats2half2_rn(v0, v1);
    __half2 h1 = __floats2half2_rn(v2, v3);
    uint2 pk = make_uint2(*reinterpret_cast<uint32_t*>(&h0),
                          *reinterpret_cast<uint32_t*>(&h1));
    *reinterpret_cast<uint2*>(O1 + i) = pk;
}

// ----------------------------------------------------------------------------
extern "C" void kernel_launch(void* const* d_in, const int* in_sizes, int n_in,
                              void* d_out, int out_size)
{
    const int*   x   = (const int*)  d_in[0];
    const float* emb = (const float*)d_in[1];
    const float* hW1 = (const float*)d_in[2];
    const float* hb1 = (const float*)d_in[3];
    const float* hW2 = (const float*)d_in[4];
    const float* hb2 = (const float*)d_in[5];
    const float* bW1 = (const float*)d_in[6];
    const float* bb1 = (const float*)d_in[7];
    const float* bW2 = (const float*)d_in[8];
    const float* bb2 = (const float*)d_in[9];
    const float* oW1 = (const float*)d_in[10];
    const float* ob1 = (const float*)d_in[11];
    const float* oW2 = (const float*)d_in[12];
    const float* ob2 = (const float*)d_in[13];
    const float* oW3 = (const float*)d_in[14];
    const float* ob3 = (const float*)d_in[15];
    const float* sW  = (const float*)d_in[16];
    const float* sb  = (const float*)d_in[17];
    float* out = (float*)d_out;

    int M = in_sizes[0] / 18;
    if (M > MAXM) M = MAXM;

    __half *ah = nullptr, *wh = nullptr;
    float* part = nullptr;
    cudaGetSymbolAddress((void**)&ah, g_ah);
    cudaGetSymbolAddress((void**)&wh, g_wh);
    cudaGetSymbolAddress((void**)&part, g_part);

    constexpr int SMEM32 = 3 * (32 + 128) * 80;             // 38400
    constexpr int SMEM16 = 3 * (16 + 128) * 80;             // 34560
    constexpr int SMEMF  = SMEM16 + 1152 * 4 + 64;          // + sW/sb staging
    cudaFuncSetAttribute((const void*)fused12_kernel,
                         cudaFuncAttributeMaxDynamicSharedMemorySize, F_SMEM);
    cudaFuncSetAttribute((const void*)hmma_gemm<32, false>,
                         cudaFuncAttributeMaxDynamicSharedMemorySize, SMEM32);
    cudaFuncSetAttribute((const void*)hmma_gemm<16, false>,
                         cudaFuncAttributeMaxDynamicSharedMemorySize, SMEM16);
    cudaFuncSetAttribute((const void*)hmma_gemm<16, true>,
                         cudaFuncAttributeMaxDynamicSharedMemorySize, SMEMF);

    prep_kernel<<<M / 4, 256>>>(x, emb, ah);

    TDArr td;
    td.d[0] = { hW1, wh + W_HW1, 128, 512, 512 };
    td.d[1] = { hW2, wh + W_HW2, 512, 128, 128 };
    td.d[2] = { bW1, wh + W_BW1, 192, 512, 512 };
    td.d[3] = { bW2, wh + W_BW2, 512, 128, 128 };
    td.d[4] = { oW2, wh + W_OW2, 512, 256, 256 };
    td.d[5] = { oW3, wh + W_OW3, 256, 127, 128 };
    prep_w_kernel<<<dim3(64, 16, 7), dim3(32, 8)>>>(td, oW1, wh);

    // fused layer1+layer2: hero (K1=128) + board (K1=192), BM=16
    {
        int yh = (6 * M) / 16;    // 768
        int yb = (10 * M) / 16;   // 1280
        FuseP ph = { ah + A_HEROIN, wh + W_HW1, hb1, wh + W_HW2, hb2,
                     ah + A_X, 128, 6, 2048, 0, yh };
        FuseP pb = { ah + A_BOARDIN, wh + W_BW1, bb1, wh + W_BW2, bb2,
                     ah + A_X, 192, 10, 2048, 768, yb };
        fused12_kernel<<<dim3(1, yh + yb), 128, F_SMEM>>>(ph, pb);
    }
    // o1: [M x 512], K=2048, split-K=2, BM=32, fp32 partials (512 CTAs)
    {
        GemmP p = { ah + A_X, wh + W_WF, nullptr, 0, nullptr, part,
                    2048, 1024, 0, 512, 0, M / 32, (size_t)M * 512,
                    nullptr, nullptr, nullptr };
        hmma_gemm<32, false><<<dim3(4, M / 32, 2), 128, SMEM32>>>(p, p);
        int total4 = (M * 512) / 4;
        reduce_o1_kernel<<<(total4 + 255) / 256, 256>>>(part, ob1, ah + A_O1,
                                                        (size_t)M * 512, total4);
    }
    // o2: [M x 256], K=512, BM=16 (256 CTAs)
    {
        GemmP p = { ah + A_O1, wh + W_OW2, ob2, 256, ah + A_O2, nullptr,
                    512, 512, 0, 256, 0, M / 16, 0, nullptr, nullptr, nullptr };
        hmma_gemm<16, false><<<dim3(2, M / 16), 128, SMEM16>>>(p, p);
    }
    // o3 + fused scorer: [M x 127] @ oW3 then 127->9, BM=16 (128 CTAs)
    {
        GemmP p = { ah + A_O2, wh + W_OW3, ob3, 127, nullptr, nullptr,
                    256, 256, 0, 128, 0, M / 16, 0, sW, sb, out };
        hmma_gemm<16, true><<<dim3(1, M / 16), 128, SMEMF>>>(p, p);
    }

    (void)out_size; (void)n_in;
}